// round 5
// baseline (speedup 1.0000x reference)
#include <cuda_runtime.h>
#include <cuda_bf16.h>
#include <cstdint>
#include <math.h>

// Fixed shapes: P=8, B=8, C=128, L=8192, k=2
#define Bn 8
#define PC 1024
#define LS 4096
#define Ln 8192
#define NSTAT 32768.f
#define NTOT 32768      // B * LS, flattened GEMM N

// ---------------- scratch (device globals; no runtime alloc) ---------------
__device__ __nv_bfloat16 g_whi[1024 * 1024];
__device__ __nv_bfloat16 g_wlo[1024 * 1024];
__device__ __nv_bfloat16 g_xhi[(size_t)NTOT * PC];  // X^T hi: [b*Ls + n][k]
__device__ __nv_bfloat16 g_xlo[(size_t)NTOT * PC];  // X^T lo
__device__ float g_mix[(size_t)Bn * PC * LS];
__device__ float g_mean[PC];
__device__ float g_rstd[PC];

// ---------------- helpers ---------------------------------------------------
__device__ __forceinline__ uint32_t smem_u32(const void* p) {
    uint32_t a;
    asm("{ .reg .u64 t; cvta.to.shared.u64 t, %1; cvt.u32.u64 %0, t; }"
        : "=r"(a) : "l"(p));
    return a;
}
#define CP16(s, g) asm volatile("cp.async.cg.shared.global [%0], [%1], 16;" :: "r"(s), "l"(g))
#define CP_COMMIT() asm volatile("cp.async.commit_group;" ::: "memory")
#define CP_WAIT1()  asm volatile("cp.async.wait_group 1;" ::: "memory")

#define LDSM4(r0, r1, r2, r3, a)                                              \
    asm volatile("ldmatrix.sync.aligned.m8n8.x4.shared.b16 {%0,%1,%2,%3}, [%4];" \
                 : "=r"(r0), "=r"(r1), "=r"(r2), "=r"(r3) : "r"(a))

#define MMA16816(c, a, b)                                                     \
    asm volatile("mma.sync.aligned.m16n8k16.row.col.f32.bf16.bf16.f32 "       \
                 "{%0,%1,%2,%3}, {%4,%5,%6,%7}, {%8,%9}, {%0,%1,%2,%3};"      \
                 : "+f"((c)[0]), "+f"((c)[1]), "+f"((c)[2]), "+f"((c)[3])     \
                 : "r"((a)[0]), "r"((a)[1]), "r"((a)[2]), "r"((a)[3]),        \
                   "r"((b)[0]), "r"((b)[1]))

// swizzled byte offset inside a 128x32 bf16 tile (64B rows, ldmatrix-safe)
__device__ __forceinline__ uint32_t swz(int r, int c) {
    return (uint32_t)(r * 64 + ((c ^ ((r >> 1) & 3)) << 4));
}

// ---------------------------------------------------------------------------
// W split: fp32 -> (hi, lo) bf16
// ---------------------------------------------------------------------------
__global__ __launch_bounds__(256) void wconv_kernel(
    const float* __restrict__ W, __nv_bfloat16* __restrict__ hi,
    __nv_bfloat16* __restrict__ lo)
{
    int i = blockIdx.x * 256 + threadIdx.x;
    float w = W[i];
    __nv_bfloat16 h = __float2bfloat16_rn(w);
    hi[i] = h;
    lo[i] = __float2bfloat16_rn(w - __bfloat162float(h));
}

// ---------------------------------------------------------------------------
// Pass 1: Haar analysis. Writes out[...,4096:] (detail synthesis, exact fp32)
// and X^T hi/lo bf16 in [b*Ls+n][k] layout for the GEMM B operand.
// ---------------------------------------------------------------------------
__global__ __launch_bounds__(256) void prep_kernel(
    const float4* __restrict__ xs4, const float* __restrict__ A,
    const float* __restrict__ S, float* __restrict__ out,
    __nv_bfloat16* __restrict__ xhi, __nv_bfloat16* __restrict__ xlo)
{
    __shared__ __nv_bfloat16 shi[64][66], slo[64][66];
    int b = blockIdx.z, kt = blockIdx.y, nt = blockIdx.x;
    int k0 = kt * 64, n0 = nt * 64;
    int p = k0 >> 7, c0 = k0 & 127;
    int tid = threadIdx.x;
    int txn = tid & 31, tyc = tid >> 5;

    float a00 = A[0], a01 = A[1], a10 = A[2], a11 = A[3];
    float s00 = S[0], s01 = S[1], s10 = S[2], s11 = S[3];
    int nloc = 2 * txn;

#pragma unroll
    for (int r = 0; r < 8; r++) {
        int cl = tyc * 8 + r;
        long rowx = (long)((p * 8 + b) * 128 + c0 + cl);
        float4 x = xs4[rowx * 2048 + (n0 >> 1) + txn];
        float sc0 = a00 * x.x + a01 * x.y, sc1 = a00 * x.z + a01 * x.w;
        float d0  = a10 * x.x + a11 * x.y, d1  = a10 * x.z + a11 * x.w;
        *(float2*)(out + rowx * Ln + LS + n0 + nloc) =
            make_float2(s00 * d0 + s01 * d1, s10 * d0 + s11 * d1);
        __nv_bfloat16 h0 = __float2bfloat16_rn(sc0);
        __nv_bfloat16 h1 = __float2bfloat16_rn(sc1);
        shi[nloc][cl] = h0;  shi[nloc + 1][cl] = h1;
        slo[nloc][cl]     = __float2bfloat16_rn(sc0 - __bfloat162float(h0));
        slo[nloc + 1][cl] = __float2bfloat16_rn(sc1 - __bfloat162float(h1));
    }
    __syncthreads();
    int kk = tid & 63, ny = tid >> 6;
#pragma unroll
    for (int w = 0; w < 16; w++) {
        int nl = ny * 16 + w;
        long off = ((long)b * LS + n0 + nl) * 1024 + k0 + kk;
        xhi[off] = shi[nl][kk];
        xlo[off] = slo[nl][kk];
    }
}

// ---------------------------------------------------------------------------
// Pass 2: bf16 HMMA GEMM with 3-term hi/lo split.
//   Y[m][n] = Whi@Xhi + Whi@Xlo + Wlo@Xhi   (fp32 accum)
// M=1024, N=32768 (flattened over b), K=1024.
// CTA tile 128x128x32, 3-stage cp.async, 8 warps (2x4), warp tile 64x32.
// ---------------------------------------------------------------------------
#define GBK 32
#define KTILES 32          // 1024 / GBK
#define TILE_B 8192        // 128 rows * 64 bytes
#define STG_B (4 * TILE_B) // Ah, Al, Bh, Bl
#define GSTG 3
#define GEMM_SMEM (GSTG * STG_B)

__device__ __forceinline__ void g_load_stage(
    uint32_t sb, int tid, int k0,
    const __nv_bfloat16* gAh, const __nv_bfloat16* gAl,
    const __nv_bfloat16* gBh, const __nv_bfloat16* gBl)
{
    // 512 16B-chunks per 128x32 tile; 2 per thread per tile
#pragma unroll
    for (int t = 0; t < 2; t++) {
        int ch = tid * 2 + t;
        int r = ch >> 2, c = ch & 3;
        uint32_t so = swz(r, c);
        long go = (long)r * 1024 + k0 + c * 8;
        CP16(sb + so,              gAh + go);
        CP16(sb + TILE_B + so,     gAl + go);
        CP16(sb + 2 * TILE_B + so, gBh + go);
        CP16(sb + 3 * TILE_B + so, gBl + go);
    }
    CP_COMMIT();
}

__global__ __launch_bounds__(256, 1) void gemm_hmma_kernel(
    const __nv_bfloat16* __restrict__ Whi, const __nv_bfloat16* __restrict__ Wlo,
    const __nv_bfloat16* __restrict__ Xhi, const __nv_bfloat16* __restrict__ Xlo,
    float* __restrict__ Y)
{
    extern __shared__ char smem[];
    uint32_t sbase = smem_u32(smem);
    int tid = threadIdx.x;
    int lane = tid & 31, wid = tid >> 5;
    int wm = wid & 1, wn = wid >> 1;        // 2 x 4 warp grid
    int m0 = blockIdx.y * 128;
    long n0g = (long)blockIdx.x * 128;

    const __nv_bfloat16* gAh = Whi + (long)m0 * 1024;
    const __nv_bfloat16* gAl = Wlo + (long)m0 * 1024;
    const __nv_bfloat16* gBh = Xhi + n0g * 1024;
    const __nv_bfloat16* gBl = Xlo + n0g * 1024;

    float acc[4][4][4];
#pragma unroll
    for (int i = 0; i < 4; i++)
#pragma unroll
        for (int j = 0; j < 4; j++)
#pragma unroll
            for (int q = 0; q < 4; q++) acc[i][j][q] = 0.f;

    // prologue: stages 0,1
    g_load_stage(sbase, tid, 0, gAh, gAl, gBh, gBl);
    g_load_stage(sbase + STG_B, tid, GBK, gAh, gAl, gBh, gBl);

    // per-lane ldmatrix address pieces
    int a_row = (lane & 15);          // + wm*64 + mt*16
    int a_kg  = lane >> 4;            // 0/1 -> +8 k
    int b_row = (lane & 7);           // + wn*32 + nt*16 + (g>>1)*8
    int b_g   = lane >> 3;

    for (int ks = 0; ks < KTILES; ks++) {
        CP_WAIT1();
        __syncthreads();
        // issue next stage (overwrites the stage finished last iteration)
        if (ks + GSTG - 1 < KTILES)
            g_load_stage(sbase + ((ks + GSTG - 1) % GSTG) * STG_B, tid,
                         (ks + GSTG - 1) * GBK, gAh, gAl, gBh, gBl);
        else
            CP_COMMIT();

        uint32_t st = sbase + (ks % GSTG) * STG_B;
        uint32_t sAh = st, sAl = st + TILE_B;
        uint32_t sBh = st + 2 * TILE_B, sBl = st + 3 * TILE_B;

#pragma unroll
        for (int kk2 = 0; kk2 < 2; kk2++) {
            uint32_t ah[4][4], al[4][4], bh[2][4], bl[2][4];
#pragma unroll
            for (int mt = 0; mt < 4; mt++) {
                int r = wm * 64 + mt * 16 + a_row;
                int c = kk2 * 2 + a_kg;
                uint32_t o = swz(r, c);
                LDSM4(ah[mt][0], ah[mt][1], ah[mt][2], ah[mt][3], sAh + o);
                LDSM4(al[mt][0], al[mt][1], al[mt][2], al[mt][3], sAl + o);
            }
#pragma unroll
            for (int nt = 0; nt < 2; nt++) {
                int r = wn * 32 + nt * 16 + (b_g >> 1) * 8 + b_row;
                int c = kk2 * 2 + (b_g & 1);
                uint32_t o = swz(r, c);
                LDSM4(bh[nt][0], bh[nt][1], bh[nt][2], bh[nt][3], sBh + o);
                LDSM4(bl[nt][0], bl[nt][1], bl[nt][2], bl[nt][3], sBl + o);
            }
#pragma unroll
            for (int mt = 0; mt < 4; mt++) {
#pragma unroll
                for (int n8 = 0; n8 < 4; n8++) {
                    uint32_t bfh[2] = { bh[n8 >> 1][(n8 & 1) * 2],
                                        bh[n8 >> 1][(n8 & 1) * 2 + 1] };
                    uint32_t bfl[2] = { bl[n8 >> 1][(n8 & 1) * 2],
                                        bl[n8 >> 1][(n8 & 1) * 2 + 1] };
                    MMA16816(acc[mt][n8], ah[mt], bfh);
                    MMA16816(acc[mt][n8], ah[mt], bfl);
                    MMA16816(acc[mt][n8], al[mt], bfh);
                }
            }
        }
        __syncthreads();
    }

    // epilogue: write to mix[b][m][ls]; whole CTA is within one b
    int bb = (int)(n0g >> 12);
    int ncol0 = (int)(n0g & 4095) + wn * 32;
    float* ybase = Y + (long)bb * PC * LS;
#pragma unroll
    for (int mt = 0; mt < 4; mt++) {
        int mrow = m0 + wm * 64 + mt * 16 + (lane >> 2);
#pragma unroll
        for (int n8 = 0; n8 < 4; n8++) {
            int col = ncol0 + n8 * 8 + (lane & 3) * 2;
            *(float2*)(ybase + (long)mrow * LS + col) =
                make_float2(acc[mt][n8][0], acc[mt][n8][1]);
            *(float2*)(ybase + (long)(mrow + 8) * LS + col) =
                make_float2(acc[mt][n8][2], acc[mt][n8][3]);
        }
    }
}

// ---------------------------------------------------------------------------
// Pass 3: BatchNorm stats per channel (biased, over B*Ls = 32768 values)
// ---------------------------------------------------------------------------
__global__ __launch_bounds__(256) void bn_stats_kernel(
    const float* __restrict__ Y, float* __restrict__ mean,
    float* __restrict__ rstd)
{
    int i = blockIdx.x;
    float s = 0.f, ss = 0.f;
    const float* base = Y + (long)i * LS;
    for (int b = 0; b < Bn; b++) {
        const float* row = base + (long)b * PC * LS;
        for (int l = threadIdx.x * 4; l < LS; l += blockDim.x * 4) {
            float4 v = *(const float4*)(row + l);
            s  += v.x + v.y + v.z + v.w;
            ss += v.x * v.x + v.y * v.y + v.z * v.z + v.w * v.w;
        }
    }
    __shared__ float shs[8], shss[8];
#pragma unroll
    for (int o = 16; o > 0; o >>= 1) {
        s  += __shfl_down_sync(0xffffffffu, s, o);
        ss += __shfl_down_sync(0xffffffffu, ss, o);
    }
    if ((threadIdx.x & 31) == 0) { shs[threadIdx.x >> 5] = s; shss[threadIdx.x >> 5] = ss; }
    __syncthreads();
    if (threadIdx.x < 8) {
        s = shs[threadIdx.x]; ss = shss[threadIdx.x];
#pragma unroll
        for (int o = 4; o > 0; o >>= 1) {
            s  += __shfl_down_sync(0xffu, s, o);
            ss += __shfl_down_sync(0xffu, ss, o);
        }
        if (threadIdx.x == 0) {
            float m = s / NSTAT;
            mean[i] = m;
            rstd[i] = rsqrtf(ss / NSTAT - m * m + 1e-5f);
        }
    }
}

// ---------------------------------------------------------------------------
// Pass 4: BN + exact GELU + scaling-half synthesis -> out[..., :4096]
// ---------------------------------------------------------------------------
__global__ __launch_bounds__(256) void final_kernel(
    const float* __restrict__ Y, const float* __restrict__ mean,
    const float* __restrict__ rstd, const float* __restrict__ gamma,
    const float* __restrict__ beta, const float* __restrict__ S,
    float* __restrict__ out)
{
    long tid = (long)blockIdx.x * blockDim.x + threadIdx.x;
    int n  = (int)(tid & 2047);
    int rj = (int)(tid >> 11);
    int b  = rj >> 10;
    int j  = rj & 1023;

    float2 v = *(const float2*)(Y + (long)rj * LS + 2 * n);
    float mu = mean[j], rs = rstd[j], ga = gamma[j], be = beta[j];
    float h0 = (v.x - mu) * rs * ga + be;
    float h1 = (v.y - mu) * rs * ga + be;
    const float inv_sqrt2 = 0.70710678118654752f;
    float g0 = 0.5f * h0 * (1.f + erff(h0 * inv_sqrt2));
    float g1 = 0.5f * h1 * (1.f + erff(h1 * inv_sqrt2));

    float s00 = S[0], s01 = S[1], s10 = S[2], s11 = S[3];
    int p = j >> 7, c = j & 127;
    long ooff = (((long)p * Bn + b) * 128 + c) * Ln + 2 * n;
    *(float2*)(out + ooff) = make_float2(s00 * g0 + s01 * g1, s10 * g0 + s11 * g1);
}

// ---------------------------------------------------------------------------
extern "C" void kernel_launch(void* const* d_in, const int* in_sizes, int n_in,
                              void* d_out, int out_size)
{
    const float* xs    = (const float*)d_in[0];
    const float* A     = (const float*)d_in[1];
    const float* S     = (const float*)d_in[2];
    const float* Wc    = (const float*)d_in[3];
    const float* gamma = (const float*)d_in[4];
    const float* beta  = (const float*)d_in[5];
    float* out = (float*)d_out;

    __nv_bfloat16 *whi, *wlo, *xhi, *xlo;
    float *mix, *mean, *rstd;
    cudaGetSymbolAddress((void**)&whi, g_whi);
    cudaGetSymbolAddress((void**)&wlo, g_wlo);
    cudaGetSymbolAddress((void**)&xhi, g_xhi);
    cudaGetSymbolAddress((void**)&xlo, g_xlo);
    cudaGetSymbolAddress((void**)&mix, g_mix);
    cudaGetSymbolAddress((void**)&mean, g_mean);
    cudaGetSymbolAddress((void**)&rstd, g_rstd);

    cudaFuncSetAttribute(gemm_hmma_kernel,
                         cudaFuncAttributeMaxDynamicSharedMemorySize, GEMM_SMEM);

    wconv_kernel<<<4096, 256>>>(Wc, whi, wlo);
    prep_kernel<<<dim3(64, 16, 8), 256>>>((const float4*)xs, A, S, out, xhi, xlo);
    gemm_hmma_kernel<<<dim3(256, 8), 256, GEMM_SMEM>>>(whi, wlo, xhi, xlo, mix);
    bn_stats_kernel<<<PC, 256>>>(mix, mean, rstd);
    final_kernel<<<65536, 256>>>(mix, mean, rstd, gamma, beta, S, out);
}

// round 7
// speedup vs baseline: 1.9825x; 1.9825x over previous
#include <cuda_runtime.h>
#include <cuda_fp16.h>
#include <cstdint>
#include <math.h>

// Fixed shapes: P=8, B=8, C=128, L=8192, k=2
#define Bn 8
#define PC 1024
#define LS 4096
#define Ln 8192
#define NSTAT 32768.f
#define NTOT 32768      // B * LS

// ---------------- scratch (device globals; no runtime alloc) ---------------
__device__ __half g_eh[1024 * 1024];                // E = W - I, fp16
__device__ __half g_xh[(size_t)NTOT * PC];          // X^T fp16: [b*Ls+n][k]
__device__ float  g_sc[(size_t)Bn * PC * LS];       // sc fp32:  [b][j][l]
__device__ float  g_mix[(size_t)Bn * PC * LS];
__device__ float  g_mean[PC];
__device__ float  g_rstd[PC];

// ---------------- helpers ---------------------------------------------------
__device__ __forceinline__ uint32_t smem_u32(const void* p) {
    uint32_t a;
    asm("{ .reg .u64 t; cvta.to.shared.u64 t, %1; cvt.u32.u64 %0, t; }"
        : "=r"(a) : "l"(p));
    return a;
}
#define CP16(s, g) asm volatile("cp.async.cg.shared.global [%0], [%1], 16;" :: "r"(s), "l"(g))
#define CP_COMMIT() asm volatile("cp.async.commit_group;" ::: "memory")
#define CP_WAIT3()  asm volatile("cp.async.wait_group 3;" ::: "memory")

#define LDSM4(r0, r1, r2, r3, a)                                              \
    asm volatile("ldmatrix.sync.aligned.m8n8.x4.shared.b16 {%0,%1,%2,%3}, [%4];" \
                 : "=r"(r0), "=r"(r1), "=r"(r2), "=r"(r3) : "r"(a))

#define MMA16816(c, a, b)                                                     \
    asm volatile("mma.sync.aligned.m16n8k16.row.col.f32.f16.f16.f32 "         \
                 "{%0,%1,%2,%3}, {%4,%5,%6,%7}, {%8,%9}, {%0,%1,%2,%3};"      \
                 : "+f"((c)[0]), "+f"((c)[1]), "+f"((c)[2]), "+f"((c)[3])     \
                 : "r"((a)[0]), "r"((a)[1]), "r"((a)[2]), "r"((a)[3]),        \
                   "r"((b)[0]), "r"((b)[1]))

// swizzled byte offset inside a 128x32 fp16 tile (64B rows, ldmatrix-safe)
__device__ __forceinline__ uint32_t swz(int r, int c) {
    return (uint32_t)(r * 64 + ((c ^ ((r >> 1) & 3)) << 4));
}

// ---------------------------------------------------------------------------
// E = W - I, fp32 -> fp16
// ---------------------------------------------------------------------------
__global__ __launch_bounds__(256) void econv_kernel(
    const float* __restrict__ W, __half* __restrict__ eh)
{
    int i = blockIdx.x * 256 + threadIdx.x;
    int r = i >> 10, c = i & 1023;
    float w = W[i];
    if (r == c) w -= 1.f;
    eh[i] = __float2half_rn(w);
}

// ---------------------------------------------------------------------------
// Pass 1: Haar analysis.
//  - out[..., 4096:]  detail-half synthesis (exact fp32)
//  - xh  fp16 X^T [b*Ls+n][k]   (GEMM B operand)
//  - scf fp32 sc  [b][j][l]     (exact identity term, added in GEMM epilogue)
// ---------------------------------------------------------------------------
__global__ __launch_bounds__(256) void prep_kernel(
    const float4* __restrict__ xs4, const float* __restrict__ A,
    const float* __restrict__ S, float* __restrict__ out,
    __half* __restrict__ xh, float* __restrict__ scf)
{
    __shared__ float  sflt[64][66];   // [channel-local][n-local]
    __shared__ __half shx[64][66];    // [n-local][channel-local]
    int b = blockIdx.z, kt = blockIdx.y, nt = blockIdx.x;
    int k0 = kt * 64, n0 = nt * 64;
    int p = k0 >> 7, c0 = k0 & 127;
    int tid = threadIdx.x;
    int txn = tid & 31, tyc = tid >> 5;

    float a00 = A[0], a01 = A[1], a10 = A[2], a11 = A[3];
    float s00 = S[0], s01 = S[1], s10 = S[2], s11 = S[3];
    int nloc = 2 * txn;

#pragma unroll
    for (int r = 0; r < 8; r++) {
        int cl = tyc * 8 + r;
        long rowx = (long)((p * 8 + b) * 128 + c0 + cl);
        float4 x = xs4[rowx * 2048 + (n0 >> 1) + txn];
        float sc0 = a00 * x.x + a01 * x.y, sc1 = a00 * x.z + a01 * x.w;
        float d0  = a10 * x.x + a11 * x.y, d1  = a10 * x.z + a11 * x.w;
        *(float2*)(out + rowx * Ln + LS + n0 + nloc) =
            make_float2(s00 * d0 + s01 * d1, s10 * d0 + s11 * d1);
        sflt[cl][nloc] = sc0;  sflt[cl][nloc + 1] = sc1;
        shx[nloc][cl] = __float2half_rn(sc0);
        shx[nloc + 1][cl] = __float2half_rn(sc1);
    }
    __syncthreads();
    int w = tid >> 5, lane = tid & 31;
#pragma unroll
    for (int r = 0; r < 8; r++) {
        int nl = w * 8 + r;   // doubles as channel-local row for scf
        __half2 hv = __halves2half2(shx[nl][2 * lane], shx[nl][2 * lane + 1]);
        *(__half2*)(xh + ((long)b * LS + n0 + nl) * 1024 + k0 + 2 * lane) = hv;
        float2 fv = make_float2(sflt[nl][2 * lane], sflt[nl][2 * lane + 1]);
        *(float2*)(scf + ((long)b * PC + k0 + nl) * LS + n0 + 2 * lane) = fv;
    }
}

// ---------------------------------------------------------------------------
// Pass 2: fp16 HMMA GEMM, single term:  Y = sc + E @ X
// M=1024, N=32768 (flat over b), K=1024. CTA 128x128x32, 5-stage cp.async,
// 8 warps (2x4), warp tile 64x32, 2 CTAs/SM.
// ---------------------------------------------------------------------------
#define GBK 32
#define KTILES 32
#define TILE_B 8192        // 128 rows * 64 bytes
#define STG_B (2 * TILE_B) // A, B
#define GSTG 5
#define GEMM_SMEM (GSTG * STG_B)  // 80 KB

__device__ __forceinline__ void g_load_stage(
    uint32_t sb, int tid, int k0,
    const __half* gA, const __half* gB)
{
#pragma unroll
    for (int t = 0; t < 2; t++) {
        int ch = tid * 2 + t;
        int r = ch >> 2, c = ch & 3;
        uint32_t so = swz(r, c);
        long go = (long)r * 1024 + k0 + c * 8;
        CP16(sb + so,          gA + go);
        CP16(sb + TILE_B + so, gB + go);
    }
    CP_COMMIT();
}

__global__ __launch_bounds__(256, 2) void gemm_hmma_kernel(
    const __half* __restrict__ E, const __half* __restrict__ X,
    const float* __restrict__ SC, float* __restrict__ Y)
{
    extern __shared__ char smem[];
    uint32_t sbase = smem_u32(smem);
    int tid = threadIdx.x;
    int lane = tid & 31, wid = tid >> 5;
    int wm = wid & 1, wn = wid >> 1;        // 2 x 4 warp grid
    int m0 = blockIdx.y * 128;
    long n0g = (long)blockIdx.x * 128;

    const __half* gA = E + (long)m0 * 1024;
    const __half* gB = X + n0g * 1024;

    float acc[4][4][4];
#pragma unroll
    for (int i = 0; i < 4; i++)
#pragma unroll
        for (int j = 0; j < 4; j++)
#pragma unroll
            for (int q = 0; q < 4; q++) acc[i][j][q] = 0.f;

    // prologue: stages 0..3
    g_load_stage(sbase,             tid, 0 * GBK, gA, gB);
    g_load_stage(sbase + 1 * STG_B, tid, 1 * GBK, gA, gB);
    g_load_stage(sbase + 2 * STG_B, tid, 2 * GBK, gA, gB);
    g_load_stage(sbase + 3 * STG_B, tid, 3 * GBK, gA, gB);

    int a_row = (lane & 15);
    int a_kg  = lane >> 4;
    int b_row = (lane & 7);
    int b_g   = lane >> 3;

    for (int ks = 0; ks < KTILES; ks++) {
        CP_WAIT3();           // stage ks resident
        __syncthreads();      // all warps done with slot being overwritten
        if (ks + 4 < KTILES)
            g_load_stage(sbase + ((ks + 4) % GSTG) * STG_B, tid,
                         (ks + 4) * GBK, gA, gB);
        else
            CP_COMMIT();      // keep group arithmetic

        uint32_t st = sbase + (ks % GSTG) * STG_B;
        uint32_t sA = st, sB = st + TILE_B;

#pragma unroll
        for (int kk2 = 0; kk2 < 2; kk2++) {
            uint32_t ah[4][4], bh[2][4];
#pragma unroll
            for (int mt = 0; mt < 4; mt++) {
                int r = wm * 64 + mt * 16 + a_row;
                int c = kk2 * 2 + a_kg;
                LDSM4(ah[mt][0], ah[mt][1], ah[mt][2], ah[mt][3], sA + swz(r, c));
            }
#pragma unroll
            for (int nt = 0; nt < 2; nt++) {
                int r = wn * 32 + nt * 16 + (b_g >> 1) * 8 + b_row;
                int c = kk2 * 2 + (b_g & 1);
                LDSM4(bh[nt][0], bh[nt][1], bh[nt][2], bh[nt][3], sB + swz(r, c));
            }
#pragma unroll
            for (int mt = 0; mt < 4; mt++) {
#pragma unroll
                for (int n8 = 0; n8 < 4; n8++) {
                    uint32_t bf[2] = { bh[n8 >> 1][(n8 & 1) * 2],
                                       bh[n8 >> 1][(n8 & 1) * 2 + 1] };
                    MMA16816(acc[mt][n8], ah[mt], bf);
                }
            }
        }
        __syncthreads();
    }

    // epilogue: Y = acc + sc (exact identity term)
    int bb = (int)(n0g >> 12);
    int ncol0 = (int)(n0g & 4095) + wn * 32;
    float* ybase = Y + (long)bb * PC * LS;
    const float* sbase_f = SC + (long)bb * PC * LS;
#pragma unroll
    for (int mt = 0; mt < 4; mt++) {
        int mrow = m0 + wm * 64 + mt * 16 + (lane >> 2);
#pragma unroll
        for (int n8 = 0; n8 < 4; n8++) {
            int col = ncol0 + n8 * 8 + (lane & 3) * 2;
            long o0 = (long)mrow * LS + col;
            long o1 = (long)(mrow + 8) * LS + col;
            float2 s0 = *(const float2*)(sbase_f + o0);
            float2 s1 = *(const float2*)(sbase_f + o1);
            *(float2*)(ybase + o0) =
                make_float2(acc[mt][n8][0] + s0.x, acc[mt][n8][1] + s0.y);
            *(float2*)(ybase + o1) =
                make_float2(acc[mt][n8][2] + s1.x, acc[mt][n8][3] + s1.y);
        }
    }
}

// ---------------------------------------------------------------------------
// Pass 3: BatchNorm stats per channel (biased, over B*Ls = 32768 values)
// ---------------------------------------------------------------------------
__global__ __launch_bounds__(256) void bn_stats_kernel(
    const float* __restrict__ Y, float* __restrict__ mean,
    float* __restrict__ rstd)
{
    int i = blockIdx.x;
    float s = 0.f, ss = 0.f;
    const float* base = Y + (long)i * LS;
    for (int b = 0; b < Bn; b++) {
        const float* row = base + (long)b * PC * LS;
        for (int l = threadIdx.x * 4; l < LS; l += blockDim.x * 4) {
            float4 v = *(const float4*)(row + l);
            s  += v.x + v.y + v.z + v.w;
            ss += v.x * v.x + v.y * v.y + v.z * v.z + v.w * v.w;
        }
    }
    __shared__ float shs[8], shss[8];
#pragma unroll
    for (int o = 16; o > 0; o >>= 1) {
        s  += __shfl_down_sync(0xffffffffu, s, o);
        ss += __shfl_down_sync(0xffffffffu, ss, o);
    }
    if ((threadIdx.x & 31) == 0) { shs[threadIdx.x >> 5] = s; shss[threadIdx.x >> 5] = ss; }
    __syncthreads();
    if (threadIdx.x < 8) {
        s = shs[threadIdx.x]; ss = shss[threadIdx.x];
#pragma unroll
        for (int o = 4; o > 0; o >>= 1) {
            s  += __shfl_down_sync(0xffu, s, o);
            ss += __shfl_down_sync(0xffu, ss, o);
        }
        if (threadIdx.x == 0) {
            float m = s / NSTAT;
            mean[i] = m;
            rstd[i] = rsqrtf(ss / NSTAT - m * m + 1e-5f);
        }
    }
}

// ---------------------------------------------------------------------------
// Pass 4: BN + exact GELU + scaling-half synthesis -> out[..., :4096]
// float4 per thread (2 output pairs)
// ---------------------------------------------------------------------------
__global__ __launch_bounds__(256) void final_kernel(
    const float* __restrict__ Y, const float* __restrict__ mean,
    const float* __restrict__ rstd, const float* __restrict__ gamma,
    const float* __restrict__ beta, const float* __restrict__ S,
    float* __restrict__ out)
{
    long tid = (long)blockIdx.x * blockDim.x + threadIdx.x;
    int n4 = (int)(tid & 1023);
    int rj = (int)(tid >> 10);
    int b  = rj >> 10;
    int j  = rj & 1023;

    float4 v = *(const float4*)(Y + (long)rj * LS + 4 * n4);
    float mu = mean[j], rs = rstd[j], ga = gamma[j], be = beta[j];
    float grs = ga * rs;
    float h0 = (v.x - mu) * grs + be;
    float h1 = (v.y - mu) * grs + be;
    float h2 = (v.z - mu) * grs + be;
    float h3 = (v.w - mu) * grs + be;
    const float is2 = 0.70710678118654752f;
    float g0 = 0.5f * h0 * (1.f + erff(h0 * is2));
    float g1 = 0.5f * h1 * (1.f + erff(h1 * is2));
    float g2 = 0.5f * h2 * (1.f + erff(h2 * is2));
    float g3 = 0.5f * h3 * (1.f + erff(h3 * is2));

    float s00 = S[0], s01 = S[1], s10 = S[2], s11 = S[3];
    int p = j >> 7, c = j & 127;
    long ooff = (((long)p * Bn + b) * 128 + c) * Ln + 4 * n4;
    *(float4*)(out + ooff) = make_float4(
        s00 * g0 + s01 * g1, s10 * g0 + s11 * g1,
        s00 * g2 + s01 * g3, s10 * g2 + s11 * g3);
}

// ---------------------------------------------------------------------------
extern "C" void kernel_launch(void* const* d_in, const int* in_sizes, int n_in,
                              void* d_out, int out_size)
{
    const float* xs    = (const float*)d_in[0];
    const float* A     = (const float*)d_in[1];
    const float* S     = (const float*)d_in[2];
    const float* Wc    = (const float*)d_in[3];
    const float* gamma = (const float*)d_in[4];
    const float* beta  = (const float*)d_in[5];
    float* out = (float*)d_out;

    __half *eh, *xh;
    float *sc, *mix, *mean, *rstd;
    cudaGetSymbolAddress((void**)&eh, g_eh);
    cudaGetSymbolAddress((void**)&xh, g_xh);
    cudaGetSymbolAddress((void**)&sc, g_sc);
    cudaGetSymbolAddress((void**)&mix, g_mix);
    cudaGetSymbolAddress((void**)&mean, g_mean);
    cudaGetSymbolAddress((void**)&rstd, g_rstd);

    cudaFuncSetAttribute(gemm_hmma_kernel,
                         cudaFuncAttributeMaxDynamicSharedMemorySize, GEMM_SMEM);

    econv_kernel<<<4096, 256>>>(Wc, eh);
    prep_kernel<<<dim3(64, 16, 8), 256>>>((const float4*)xs, A, S, out, xh, sc);
    gemm_hmma_kernel<<<dim3(256, 8), 256, GEMM_SMEM>>>(eh, xh, sc, mix);
    bn_stats_kernel<<<PC, 256>>>(mix, mean, rstd);
    final_kernel<<<32768, 256>>>(mix, mean, rstd, gamma, beta, S, out);
}